// round 7
// baseline (speedup 1.0000x reference)
#include <cuda_runtime.h>
#include <cuda_bf16.h>
#include <math.h>
#include <stdint.h>

// ---------------- problem caps (fixed shapes: B=4096, D=2048, C=1000) ----------------
#define D_CAP   2048
#define KEXT_CAP (3 * D_CAP)           // 6144 (split-bf16 K extension)
#define MP_CAP  5120                   // ceil(5096/256)*256
#define CP_CAP  1024
#define N_CAP   6144
#define SCAP    1536

// ---------------- static scratch ----------------
__device__ __nv_bfloat16 g_Sext[(size_t)MP_CAP * KEXT_CAP];   // [hi|lo|hi] supports [W;z]
__device__ __nv_bfloat16 g_Bext[(size_t)CP_CAP * KEXT_CAP];   // [hi|hi|lo] of W
__device__ __nv_bfloat16 g_wText[(size_t)CP_CAP * KEXT_CAP];  // [hi|hi|lo] of weights^T
__device__ float g_logits[(size_t)MP_CAP * CP_CAP];           // ld = CP_CAP
__device__ float g_rnorm[N_CAP];
__device__ float g_ent[N_CAP];
__device__ int   g_yhat[N_CAP];
__device__ float g_wT[(size_t)CP_CAP * D_CAP];                // fp32 [C, D]

// ---------------- helpers ----------------
__device__ __forceinline__ uint32_t smem_u32(const void* p) {
    uint32_t a;
    asm("{ .reg .u64 t; cvta.to.shared.u64 t, %1; cvt.u32.u64 %0, t; }" : "=r"(a) : "l"(p));
    return a;
}
__device__ __forceinline__ uint32_t sw64(uint32_t off) { return off ^ ((off >> 3) & 0x30); }

#define CP_ASYNC16(dst, src) \
    asm volatile("cp.async.cg.shared.global [%0], [%1], 16;" :: "r"(dst), "l"(src))
#define CP_COMMIT() asm volatile("cp.async.commit_group;" ::: "memory")
#define CP_WAIT(n)  asm volatile("cp.async.wait_group %0;" :: "n"(n) : "memory")

__device__ __forceinline__ void ldsm4(uint32_t* r, uint32_t addr) {
    asm volatile("ldmatrix.sync.aligned.m8n8.x4.shared.b16 {%0,%1,%2,%3}, [%4];"
                 : "=r"(r[0]), "=r"(r[1]), "=r"(r[2]), "=r"(r[3]) : "r"(addr));
}
__device__ __forceinline__ void mma16816(float* c, const uint32_t* a, const uint32_t* b) {
    asm volatile("mma.sync.aligned.m16n8k16.row.col.f32.bf16.bf16.f32 "
                 "{%0,%1,%2,%3}, {%4,%5,%6,%7}, {%8,%9}, {%0,%1,%2,%3};"
                 : "+f"(c[0]), "+f"(c[1]), "+f"(c[2]), "+f"(c[3])
                 : "r"(a[0]), "r"(a[1]), "r"(a[2]), "r"(a[3]), "r"(b[0]), "r"(b[1]));
}

// ---------------- split-bf16 operand build + fused row norms ----------------
__global__ void conv_supports_kernel(const float* __restrict__ z, const float* __restrict__ W,
                                     int Bn, int Cn, int Nn, int Dn, int Kext) {
    int row = blockIdx.x;
    const float* src = (row < Cn) ? (W + (size_t)row * Dn)
                                  : ((row < Nn) ? (z + (size_t)(row - Cn) * Dn) : nullptr);
    __nv_bfloat16* Sr = g_Sext + (size_t)row * Kext;
    __nv_bfloat16* Br = (row < CP_CAP) ? (g_Bext + (size_t)row * Kext) : nullptr;
    float ss = 0.f;
    for (int d = threadIdx.x; d < Dn; d += blockDim.x) {
        float x = src ? src[d] : 0.f;
        ss += x * x;
        __nv_bfloat16 hi = __float2bfloat16(x);
        __nv_bfloat16 lo = __float2bfloat16(x - __bfloat162float(hi));
        Sr[d] = hi; Sr[Dn + d] = lo; Sr[2 * Dn + d] = hi;
        if (Br) {
            bool v = (row < Cn);
            __nv_bfloat16 zb = __float2bfloat16(0.f);
            Br[d] = v ? hi : zb; Br[Dn + d] = v ? hi : zb; Br[2 * Dn + d] = v ? lo : zb;
        }
    }
    __shared__ float red[256];
    red[threadIdx.x] = ss;
    __syncthreads();
    for (int s = 128; s > 0; s >>= 1) {
        if (threadIdx.x < s) red[threadIdx.x] += red[threadIdx.x + s];
        __syncthreads();
    }
    if (threadIdx.x == 0 && row < Nn) g_rnorm[row] = 1.f / fmaxf(sqrtf(red[0]), 1e-12f);
}

__global__ void conv_w_kernel(int Cn, int Dn, int Kext) {
    int row = blockIdx.x;
    const float* src = (row < Cn) ? (g_wT + (size_t)row * Dn) : nullptr;
    __nv_bfloat16* Br = g_wText + (size_t)row * Kext;
    for (int d = threadIdx.x; d < Dn; d += blockDim.x) {
        float x = src ? src[d] : 0.f;
        __nv_bfloat16 hi = __float2bfloat16(x);
        __nv_bfloat16 lo = __float2bfloat16(x - __bfloat162float(hi));
        Br[d] = hi; Br[Dn + d] = hi; Br[2 * Dn + d] = lo;
    }
}

// ---------------- bf16 HMMA GEMM: C[M,N] = A[M,K] * B[N,K]^T ----------------
// 256x128 CTA tile, BK=32, 4-stage cp.async (prefetch 3, one sync/iter),
// SW64 smem, 8 warps (4x2), warp tile 64x64, occupancy 1.
#define STAGE_BYTES 24576    // A 16KB + B 8KB
#define STAGES 4

__global__ __launch_bounds__(256, 1)
void gemm_mma_kernel(const __nv_bfloat16* __restrict__ A, const __nv_bfloat16* __restrict__ B,
                     float* __restrict__ C, int ldc, int nvalid, int Kext) {
    extern __shared__ char smem[];
    const uint32_t sb = smem_u32(smem);
    const int tid = threadIdx.x;
    const int wid = tid >> 5, lane = tid & 31;
    const int wm = wid >> 1, wn = wid & 1;    // 4x2 warp grid, warp tile 64x64

    const size_t tm = (size_t)blockIdx.y * 256;
    const size_t tn = (size_t)blockIdx.x * 128;
    const __nv_bfloat16* Ab = A + tm * Kext;
    const __nv_bfloat16* Bb = B + tn * Kext;
    const int niter = Kext >> 5;

    // loader: A rows {t>>2 + 64j, j=0..3}, B rows {t>>2, t>>2+64}; chunk t&3.
    // 256 threads * 6 * 16B = 24KB = full stage.
    const int lr = tid >> 2, lc = tid & 3;
    const uint32_t l_st = sw64((uint32_t)(lr * 64 + lc * 16));  // +4096 swizzle-invariant
    const char* a_src = (const char*)(Ab + (size_t)lr * Kext + lc * 8);
    const char* b_src = (const char*)(Bb + (size_t)lr * Kext + lc * 8);
    const size_t rstep = (size_t)64 * Kext * 2;  // 64 rows in bytes

#define LOADST(it, buf) do {                                        \
        uint32_t _o = sb + (uint32_t)(buf) * STAGE_BYTES;           \
        size_t _k = (size_t)(it) * 64;                              \
        CP_ASYNC16(_o + l_st,         a_src + _k);                  \
        CP_ASYNC16(_o + l_st + 4096,  a_src + _k + rstep);          \
        CP_ASYNC16(_o + l_st + 8192,  a_src + _k + 2 * rstep);      \
        CP_ASYNC16(_o + l_st + 12288, a_src + _k + 3 * rstep);      \
        CP_ASYNC16(_o + l_st + 16384, b_src + _k);                  \
        CP_ASYNC16(_o + l_st + 20480, b_src + _k + rstep);          \
        CP_COMMIT();                                                \
    } while (0)

    // ldmatrix per-lane base addresses (ks=0, mt=0/ntp=0)
    const int mat = lane >> 3, rin = lane & 7;
    const uint32_t a_lm = sw64((uint32_t)((wm * 64 + (mat & 1) * 8 + rin) * 64 + (mat >> 1) * 16));
    const uint32_t b_lm = 16384 + sw64((uint32_t)((wn * 64 + (mat >> 1) * 8 + rin) * 64 + (mat & 1) * 16));

    float acc[4][8][4];
#pragma unroll
    for (int i = 0; i < 4; i++)
#pragma unroll
        for (int j = 0; j < 8; j++)
#pragma unroll
            for (int k = 0; k < 4; k++) acc[i][j][k] = 0.f;

    LOADST(0, 0);
    LOADST(1, 1);
    LOADST(2, 2);

    for (int it = 0; it < niter; it++) {
        CP_WAIT(2);
        __syncthreads();
        if (it + 3 < niter) LOADST(it + 3, (it + 3) & 3);
        else CP_COMMIT();
        {
            const uint32_t base = sb + (uint32_t)(it & 3) * STAGE_BYTES;
#pragma unroll
            for (int ks = 0; ks < 2; ks++) {
                uint32_t ar[4][4], br[8][2];
#pragma unroll
                for (int mt = 0; mt < 4; mt++)
                    ldsm4(ar[mt], base + ((a_lm + mt * 1024u) ^ (ks << 5)));
#pragma unroll
                for (int ntp = 0; ntp < 4; ntp++) {
                    uint32_t r[4];
                    ldsm4(r, base + ((b_lm + ntp * 1024u) ^ (ks << 5)));
                    br[2 * ntp][0] = r[0]; br[2 * ntp][1] = r[1];
                    br[2 * ntp + 1][0] = r[2]; br[2 * ntp + 1][1] = r[3];
                }
#pragma unroll
                for (int mt = 0; mt < 4; mt++)
#pragma unroll
                    for (int nt = 0; nt < 8; nt++)
                        mma16816(acc[mt][nt], ar[mt], br[nt]);
            }
        }
    }

    // epilogue
    const int r0 = lane >> 2, c0 = (lane & 3) * 2;
#pragma unroll
    for (int mt = 0; mt < 4; mt++) {
#pragma unroll
        for (int nt = 0; nt < 8; nt++) {
            size_t row = tm + wm * 64 + mt * 16 + r0;
            int col = (int)tn + wn * 64 + nt * 8 + c0;
            if (col < nvalid) {
                float2 v0 = make_float2(acc[mt][nt][0], acc[mt][nt][1]);
                float2 v1 = make_float2(acc[mt][nt][2], acc[mt][nt][3]);
                *(float2*)&C[row * (size_t)ldc + col] = v0;
                *(float2*)&C[(row + 8) * (size_t)ldc + col] = v1;
            }
        }
    }
#undef LOADST
}

// ---------------- per-row entropy + argmax (logits register-cached) ----------------
__global__ void ent_argmax_kernel(const float* __restrict__ L, int Nrows, int Cn, int ldl) {
    int row = blockIdx.x;
    const float* Lr = L + (size_t)row * ldl;
    int t = threadIdx.x;

    float vreg[4];
    float bm = -1e38f;
    int bi = 0x7fffffff;
#pragma unroll
    for (int jj = 0; jj < 4; jj++) {
        int j = t + (jj << 8);
        float v = (j < Cn) ? Lr[j] : -1e38f;
        vreg[jj] = v;
        if (v > bm || (v == bm && j < bi)) { bm = v; bi = j; }
    }
    __shared__ float sv[256];
    __shared__ float sw[256];
    __shared__ int si[256];
    sv[t] = bm; si[t] = bi;
    __syncthreads();
    for (int s = 128; s > 0; s >>= 1) {
        if (t < s) {
            float v2 = sv[t + s]; int i2 = si[t + s];
            if (v2 > sv[t] || (v2 == sv[t] && i2 < si[t])) { sv[t] = v2; si[t] = i2; }
        }
        __syncthreads();
    }
    float m = sv[0];
    int best = si[0];
    __syncthreads();

    float s0 = 0.f, s1 = 0.f;
#pragma unroll
    for (int jj = 0; jj < 4; jj++) {
        int j = t + (jj << 8);
        if (j < Cn) {
            float v = vreg[jj];
            float e = expf(v - m);
            s0 += e; s1 += v * e;
        }
    }
    sv[t] = s0; sw[t] = s1;
    __syncthreads();
    for (int s = 128; s > 0; s >>= 1) {
        if (t < s) { sv[t] += sv[t + s]; sw[t] += sw[t + s]; }
        __syncthreads();
    }
    if (t == 0) {
        float S0 = sv[0], S1 = sw[0];
        g_ent[row] = m + logf(S0) - S1 / S0;
        g_yhat[row] = best;
    }
}

// ---------------- per-class select + normalized prototype ----------------
// Compaction: per-thread contiguous chunks + one block exclusive scan (deterministic order).
__global__ void build_weights_kernel(const float* __restrict__ z, const float* __restrict__ W,
                                     int Nrows, int Bn, int Cn, int Dn,
                                     const int* __restrict__ pK) {
    const int c = blockIdx.x;
    const int t = threadIdx.x;
    const int K = *pK;

    __shared__ int s_idx[SCAP];
    __shared__ float s_ent[SCAP];
    __shared__ unsigned char s_sel[SCAP];
    __shared__ int s_scan[512];
    __shared__ float s_scale;
    __shared__ float red[256];

    const int chunk = (Nrows + 255) >> 8;         // 20 for N=5096
    const int lo = t * chunk;
    const int hi = min(lo + chunk, Nrows);

    int cnt_t = 0;
    for (int i = lo; i < hi; i++) cnt_t += (g_yhat[i] == c);

    // block exclusive scan (Hillis-Steele, double buffer)
    s_scan[t] = cnt_t;
    __syncthreads();
    int src_half = 0;
#pragma unroll
    for (int s = 1; s < 256; s <<= 1) {
        int v = s_scan[src_half * 256 + t];
        if (t >= s) v += s_scan[src_half * 256 + t - s];
        s_scan[(1 - src_half) * 256 + t] = v;
        src_half ^= 1;
        __syncthreads();
    }
    const int incl = s_scan[src_half * 256 + t];
    const int cnt = s_scan[src_half * 256 + 255];
    int pos = incl - cnt_t;                        // exclusive offset
    for (int i = lo; i < hi; i++) {
        if (g_yhat[i] == c) {
            if (pos < SCAP) { s_idx[pos] = i; s_ent[pos] = g_ent[i]; }
            pos++;
        }
    }
    __syncthreads();

    const int listn = (cnt < SCAP) ? cnt : SCAP;

    if (cnt <= K) {
        for (int m = t; m < listn; m += 256) s_sel[m] = 1;
    } else {
        for (int m = t; m < listn; m += 256) {
            float e = s_ent[m];
            int id = s_idx[m];
            int r = 0;
            for (int j = 0; j < listn; j++) {
                float ej = s_ent[j];
                r += (ej < e) || (ej == e && s_idx[j] < id);
            }
            s_sel[m] = (r < K) ? 1 : 0;
        }
    }
    __syncthreads();

    const int DPT = Dn >> 8;
    float acc[8];
#pragma unroll
    for (int j = 0; j < 8; j++) acc[j] = 0.f;

    for (int m = 0; m < listn; m++) {
        if (!s_sel[m]) continue;
        int i = s_idx[m];
        float rs = g_rnorm[i];
        const float* Sp = (i < Cn) ? (W + (size_t)i * Dn) : (z + (size_t)(i - Cn) * Dn);
#pragma unroll
        for (int j = 0; j < 8; j++)
            if (j < DPT) acc[j] += Sp[t + (j << 8)] * rs;
    }

    float ss = 0.f;
#pragma unroll
    for (int j = 0; j < 8; j++)
        if (j < DPT) ss += acc[j] * acc[j];
    red[t] = ss;
    __syncthreads();
    for (int s = 128; s > 0; s >>= 1) {
        if (t < s) red[t] += red[t + s];
        __syncthreads();
    }
    if (t == 0) s_scale = 1.f / fmaxf(sqrtf(red[0]), 1e-12f);
    __syncthreads();
    float sc = s_scale;
#pragma unroll
    for (int j = 0; j < 8; j++)
        if (j < DPT) g_wT[(size_t)c * Dn + t + (j << 8)] = acc[j] * sc;
}

// ---------------- launch ----------------
extern "C" void kernel_launch(void* const* d_in, const int* in_sizes, int n_in,
                              void* d_out, int out_size) {
    const float* z = (const float*)d_in[0];
    const float* W = (const float*)d_in[1];
    const int* pK = (const int*)d_in[2];

    double dd = sqrt((double)in_sizes[0] * (double)in_sizes[1] / (double)out_size);
    int Dn = (int)(dd + 0.5);
    int Bn = in_sizes[0] / Dn;
    int Cn = in_sizes[1] / Dn;
    int Nn = Bn + Cn;
    int Kext = 3 * Dn;
    int Mp = ((Nn + 255) / 256) * 256;   // 5120
    int Cp = ((Cn + 127) / 128) * 128;   // 1024

    __nv_bfloat16 *Sp, *Bp, *Wp;
    float* Lp;
    cudaGetSymbolAddress((void**)&Sp, g_Sext);
    cudaGetSymbolAddress((void**)&Bp, g_Bext);
    cudaGetSymbolAddress((void**)&Wp, g_wText);
    cudaGetSymbolAddress((void**)&Lp, g_logits);

    cudaFuncSetAttribute(gemm_mma_kernel, cudaFuncAttributeMaxDynamicSharedMemorySize,
                         STAGES * STAGE_BYTES);

    // 1. split-bf16 operands + fused row norms
    conv_supports_kernel<<<Mp, 256>>>(z, W, Bn, Cn, Nn, Dn, Kext);

    // 2. logits = [W;z] @ W^T   (grid 8 x 20)
    {
        dim3 g(Cp / 128, Mp / 256);
        gemm_mma_kernel<<<g, 256, STAGES * STAGE_BYTES>>>(Sp, Bp, Lp, CP_CAP, Cn, Kext);
    }

    // 3. entropy + argmax
    ent_argmax_kernel<<<Nn, 256>>>(Lp, Nn, Cn, CP_CAP);

    // 4. per-class selection + prototypes
    build_weights_kernel<<<Cn, 256>>>(z, W, Nn, Bn, Cn, Dn, pK);

    // 5. weights -> split-bf16, then out = z @ weights   (grid 8 x 16)
    conv_w_kernel<<<Cp, 256>>>(Cn, Dn, Kext);
    {
        dim3 g(Cp / 128, Bn / 256);
        gemm_mma_kernel<<<g, 256, STAGES * STAGE_BYTES>>>(Sp + (size_t)Cn * Kext, Wp,
                                                          (float*)d_out, Cn, Cn, Kext);
    }
}

// round 8
// speedup vs baseline: 1.2595x; 1.2595x over previous
#include <cuda_runtime.h>
#include <cuda_bf16.h>
#include <math.h>
#include <stdint.h>

// ---------------- problem caps (fixed shapes: B=4096, D=2048, C=1000) ----------------
#define D_CAP   2048
#define K2_CAP  (2 * D_CAP)            // stored operand width: [hi | lo]
#define MP_CAP  5120
#define CP_CAP  1024
#define N_CAP   6144
#define SCAP    1536

// ---------------- static scratch ----------------
__device__ __nv_bfloat16 g_Sext[(size_t)MP_CAP * K2_CAP];    // [hi|lo] supports [W;z]
__device__ __nv_bfloat16 g_Bext[(size_t)CP_CAP * K2_CAP];    // [hi|lo] of W
__device__ __nv_bfloat16 g_wText[(size_t)CP_CAP * K2_CAP];   // [hi|lo] of weights^T
__device__ float g_logits[(size_t)MP_CAP * CP_CAP];          // ld = CP_CAP
__device__ float g_rnorm[N_CAP];
__device__ float g_ent[N_CAP];
__device__ int   g_yhat[N_CAP];
__device__ float g_wT[(size_t)CP_CAP * D_CAP];               // fp32 [C, D]

// ---------------- helpers ----------------
__device__ __forceinline__ uint32_t smem_u32(const void* p) {
    uint32_t a;
    asm("{ .reg .u64 t; cvta.to.shared.u64 t, %1; cvt.u32.u64 %0, t; }" : "=r"(a) : "l"(p));
    return a;
}
__device__ __forceinline__ uint32_t sw64(uint32_t off) { return off ^ ((off >> 3) & 0x30); }

#define CP_ASYNC16(dst, src) \
    asm volatile("cp.async.cg.shared.global [%0], [%1], 16;" :: "r"(dst), "l"(src))
#define CP_COMMIT() asm volatile("cp.async.commit_group;" ::: "memory")
#define CP_WAIT(n)  asm volatile("cp.async.wait_group %0;" :: "n"(n) : "memory")

__device__ __forceinline__ void ldsm4(uint32_t* r, uint32_t addr) {
    asm volatile("ldmatrix.sync.aligned.m8n8.x4.shared.b16 {%0,%1,%2,%3}, [%4];"
                 : "=r"(r[0]), "=r"(r[1]), "=r"(r[2]), "=r"(r[3]) : "r"(addr));
}
__device__ __forceinline__ void mma16816(float* c, const uint32_t* a, const uint32_t* b) {
    asm volatile("mma.sync.aligned.m16n8k16.row.col.f32.bf16.bf16.f32 "
                 "{%0,%1,%2,%3}, {%4,%5,%6,%7}, {%8,%9}, {%0,%1,%2,%3};"
                 : "+f"(c[0]), "+f"(c[1]), "+f"(c[2]), "+f"(c[3])
                 : "r"(a[0]), "r"(a[1]), "r"(a[2]), "r"(a[3]), "r"(b[0]), "r"(b[1]));
}

// ---------------- split-bf16 operand build ([hi|lo]) + fused row norms ----------------
__global__ void conv_supports_kernel(const float* __restrict__ z, const float* __restrict__ W,
                                     int Bn, int Cn, int Nn, int Dn) {
    int row = blockIdx.x;
    const float* src = (row < Cn) ? (W + (size_t)row * Dn)
                                  : ((row < Nn) ? (z + (size_t)(row - Cn) * Dn) : nullptr);
    __nv_bfloat16* Sr = g_Sext + (size_t)row * (2 * Dn);
    __nv_bfloat16* Br = (row < CP_CAP) ? (g_Bext + (size_t)row * (2 * Dn)) : nullptr;
    float ss = 0.f;
    for (int d = threadIdx.x; d < Dn; d += blockDim.x) {
        float x = src ? src[d] : 0.f;
        ss += x * x;
        __nv_bfloat16 hi = __float2bfloat16(x);
        __nv_bfloat16 lo = __float2bfloat16(x - __bfloat162float(hi));
        Sr[d] = hi; Sr[Dn + d] = lo;
        if (Br) {
            bool v = (row < Cn);
            __nv_bfloat16 zb = __float2bfloat16(0.f);
            Br[d] = v ? hi : zb; Br[Dn + d] = v ? lo : zb;
        }
    }
    __shared__ float red[256];
    red[threadIdx.x] = ss;
    __syncthreads();
    for (int s = 128; s > 0; s >>= 1) {
        if (threadIdx.x < s) red[threadIdx.x] += red[threadIdx.x + s];
        __syncthreads();
    }
    if (threadIdx.x == 0 && row < Nn) g_rnorm[row] = 1.f / fmaxf(sqrtf(red[0]), 1e-12f);
}

__global__ void conv_w_kernel(int Cn, int Dn) {
    int row = blockIdx.x;
    const float* src = (row < Cn) ? (g_wT + (size_t)row * Dn) : nullptr;
    __nv_bfloat16* Br = g_wText + (size_t)row * (2 * Dn);
    for (int d = threadIdx.x; d < Dn; d += blockDim.x) {
        float x = src ? src[d] : 0.f;
        __nv_bfloat16 hi = __float2bfloat16(x);
        __nv_bfloat16 lo = __float2bfloat16(x - __bfloat162float(hi));
        Br[d] = hi; Br[Dn + d] = lo;
    }
}

// ---------------- bf16 HMMA GEMM with k-remap ----------------
// Logical K = 3D: A reads [hi|lo|hi] via k>=2D -> k-2D; B reads [hi|hi|lo] via k>=D -> k-D.
// 128x128 tile, BK=32, 4-stage cp.async (prefetch 3, one sync/iter), SW64, 8 warps (2x4).
#define STAGE_BYTES 16384    // A 8KB + B 8KB
#define STAGES 4

__global__ __launch_bounds__(256, 2)
void gemm_mma_kernel(const __nv_bfloat16* __restrict__ A, const __nv_bfloat16* __restrict__ B,
                     float* __restrict__ C, int ldc, int nvalid, int Dn) {
    extern __shared__ char smem[];
    const uint32_t sb = smem_u32(smem);
    const int tid = threadIdx.x;
    const int wid = tid >> 5, lane = tid & 31;
    const int wm = wid >> 2, wn = wid & 3;
    const int K2 = 2 * Dn;
    const int niter = (3 * Dn) >> 5;
    const int wrapA = 2 * Dn;

    const size_t tm = (size_t)blockIdx.y * 128;
    const size_t tn = (size_t)blockIdx.x * 128;
    const __nv_bfloat16* Ab = A + tm * K2;
    const __nv_bfloat16* Bb = B + tn * K2;

    // loader: thread t covers rows {t>>2, t>>2+64}, 16B chunk t&3, for A and B.
    const int lr = tid >> 2, lc = tid & 3;
    const uint32_t a_st = sw64((uint32_t)(lr * 64 + lc * 16));   // +4096 swizzle-invariant
    const uint32_t b_st = 8192 + a_st;
    const char* a_src0 = (const char*)(Ab + (size_t)lr * K2 + lc * 8);
    const char* a_src1 = (const char*)(Ab + (size_t)(lr + 64) * K2 + lc * 8);
    const char* b_src0 = (const char*)(Bb + (size_t)lr * K2 + lc * 8);
    const char* b_src1 = (const char*)(Bb + (size_t)(lr + 64) * K2 + lc * 8);

#define LOADST(it, buf) do {                                        \
        uint32_t _o = sb + (uint32_t)(buf) * STAGE_BYTES;           \
        int _k = (it) * 32;                                         \
        size_t _ka = (size_t)(_k >= wrapA ? _k - wrapA : _k) * 2;   \
        size_t _kb = (size_t)(_k >= Dn ? _k - Dn : _k) * 2;         \
        CP_ASYNC16(_o + a_st,        a_src0 + _ka);                 \
        CP_ASYNC16(_o + a_st + 4096, a_src1 + _ka);                 \
        CP_ASYNC16(_o + b_st,        b_src0 + _kb);                 \
        CP_ASYNC16(_o + b_st + 4096, b_src1 + _kb);                 \
        CP_COMMIT();                                                \
    } while (0)

    // ldmatrix per-lane base addresses (ks=0, mt=0/ntp=0)
    const int mat = lane >> 3, rin = lane & 7;
    const uint32_t a_lm = sw64((uint32_t)((wm * 64 + (mat & 1) * 8 + rin) * 64 + (mat >> 1) * 16));
    const uint32_t b_lm = 8192 + sw64((uint32_t)((wn * 32 + (mat >> 1) * 8 + rin) * 64 + (mat & 1) * 16));

    float acc[4][4][4];
#pragma unroll
    for (int i = 0; i < 4; i++)
#pragma unroll
        for (int j = 0; j < 4; j++)
#pragma unroll
            for (int k = 0; k < 4; k++) acc[i][j][k] = 0.f;

    LOADST(0, 0);
    LOADST(1, 1);
    LOADST(2, 2);

    for (int it = 0; it < niter; it++) {
        CP_WAIT(2);            // stage it resident
        __syncthreads();       // stage it visible; stage (it-1) consumed
        if (it + 3 < niter) LOADST(it + 3, (it + 3) & 3);
        else CP_COMMIT();
        {
            const uint32_t base = sb + (uint32_t)(it & 3) * STAGE_BYTES;
#pragma unroll
            for (int ks = 0; ks < 2; ks++) {
                uint32_t ar[4][4], br[4][2];
#pragma unroll
                for (int mt = 0; mt < 4; mt++)
                    ldsm4(ar[mt], base + ((a_lm + mt * 1024u) ^ (ks << 5)));
#pragma unroll
                for (int ntp = 0; ntp < 2; ntp++) {
                    uint32_t r[4];
                    ldsm4(r, base + ((b_lm + ntp * 1024u) ^ (ks << 5)));
                    br[2 * ntp][0] = r[0]; br[2 * ntp][1] = r[1];
                    br[2 * ntp + 1][0] = r[2]; br[2 * ntp + 1][1] = r[3];
                }
#pragma unroll
                for (int mt = 0; mt < 4; mt++)
#pragma unroll
                    for (int nt = 0; nt < 4; nt++)
                        mma16816(acc[mt][nt], ar[mt], br[nt]);
            }
        }
    }

    // epilogue
    const int r0 = lane >> 2, c0 = (lane & 3) * 2;
#pragma unroll
    for (int mt = 0; mt < 4; mt++) {
#pragma unroll
        for (int nt = 0; nt < 4; nt++) {
            size_t row = tm + wm * 64 + mt * 16 + r0;
            int col = (int)tn + wn * 32 + nt * 8 + c0;
            if (col < nvalid) {
                float2 v0 = make_float2(acc[mt][nt][0], acc[mt][nt][1]);
                float2 v1 = make_float2(acc[mt][nt][2], acc[mt][nt][3]);
                *(float2*)&C[row * (size_t)ldc + col] = v0;
                *(float2*)&C[(row + 8) * (size_t)ldc + col] = v1;
            }
        }
    }
#undef LOADST
}

// ---------------- per-row entropy + argmax (logits register-cached) ----------------
__global__ void ent_argmax_kernel(const float* __restrict__ L, int Nrows, int Cn, int ldl) {
    int row = blockIdx.x;
    const float* Lr = L + (size_t)row * ldl;
    int t = threadIdx.x;

    float vreg[4];
    float bm = -1e38f;
    int bi = 0x7fffffff;
#pragma unroll
    for (int jj = 0; jj < 4; jj++) {
        int j = t + (jj << 8);
        float v = (j < Cn) ? Lr[j] : -1e38f;
        vreg[jj] = v;
        if (v > bm || (v == bm && j < bi)) { bm = v; bi = j; }
    }
    __shared__ float sv[256];
    __shared__ float sw[256];
    __shared__ int si[256];
    sv[t] = bm; si[t] = bi;
    __syncthreads();
    for (int s = 128; s > 0; s >>= 1) {
        if (t < s) {
            float v2 = sv[t + s]; int i2 = si[t + s];
            if (v2 > sv[t] || (v2 == sv[t] && i2 < si[t])) { sv[t] = v2; si[t] = i2; }
        }
        __syncthreads();
    }
    float m = sv[0];
    int best = si[0];
    __syncthreads();

    float s0 = 0.f, s1 = 0.f;
#pragma unroll
    for (int jj = 0; jj < 4; jj++) {
        int j = t + (jj << 8);
        if (j < Cn) {
            float v = vreg[jj];
            float e = expf(v - m);
            s0 += e; s1 += v * e;
        }
    }
    sv[t] = s0; sw[t] = s1;
    __syncthreads();
    for (int s = 128; s > 0; s >>= 1) {
        if (t < s) { sv[t] += sv[t + s]; sw[t] += sw[t + s]; }
        __syncthreads();
    }
    if (t == 0) {
        float S0 = sv[0], S1 = sw[0];
        g_ent[row] = m + logf(S0) - S1 / S0;
        g_yhat[row] = best;
    }
}

// ---------------- per-class select + normalized prototype ----------------
__global__ void build_weights_kernel(const float* __restrict__ z, const float* __restrict__ W,
                                     int Nrows, int Bn, int Cn, int Dn,
                                     const int* __restrict__ pK) {
    const int c = blockIdx.x;
    const int t = threadIdx.x;
    const int K = *pK;

    __shared__ int s_idx[SCAP];
    __shared__ float s_ent[SCAP];
    __shared__ unsigned char s_sel[SCAP];
    __shared__ int s_scan[512];
    __shared__ float s_scale;
    __shared__ float red[256];

    const int chunk = (Nrows + 255) >> 8;
    const int lo = t * chunk;
    const int hi = min(lo + chunk, Nrows);

    int cnt_t = 0;
    for (int i = lo; i < hi; i++) cnt_t += (g_yhat[i] == c);

    s_scan[t] = cnt_t;
    __syncthreads();
    int src_half = 0;
#pragma unroll
    for (int s = 1; s < 256; s <<= 1) {
        int v = s_scan[src_half * 256 + t];
        if (t >= s) v += s_scan[src_half * 256 + t - s];
        s_scan[(1 - src_half) * 256 + t] = v;
        src_half ^= 1;
        __syncthreads();
    }
    const int incl = s_scan[src_half * 256 + t];
    const int cnt = s_scan[src_half * 256 + 255];
    int pos = incl - cnt_t;
    for (int i = lo; i < hi; i++) {
        if (g_yhat[i] == c) {
            if (pos < SCAP) { s_idx[pos] = i; s_ent[pos] = g_ent[i]; }
            pos++;
        }
    }
    __syncthreads();

    const int listn = (cnt < SCAP) ? cnt : SCAP;

    if (cnt <= K) {
        for (int m = t; m < listn; m += 256) s_sel[m] = 1;
    } else {
        for (int m = t; m < listn; m += 256) {
            float e = s_ent[m];
            int id = s_idx[m];
            int r = 0;
            for (int j = 0; j < listn; j++) {
                float ej = s_ent[j];
                r += (ej < e) || (ej == e && s_idx[j] < id);
            }
            s_sel[m] = (r < K) ? 1 : 0;
        }
    }
    __syncthreads();

    const int DPT = Dn >> 8;
    float acc[8];
#pragma unroll
    for (int j = 0; j < 8; j++) acc[j] = 0.f;

    for (int m = 0; m < listn; m++) {
        if (!s_sel[m]) continue;
        int i = s_idx[m];
        float rs = g_rnorm[i];
        const float* Sp = (i < Cn) ? (W + (size_t)i * Dn) : (z + (size_t)(i - Cn) * Dn);
#pragma unroll
        for (int j = 0; j < 8; j++)
            if (j < DPT) acc[j] += Sp[t + (j << 8)] * rs;
    }

    float ss = 0.f;
#pragma unroll
    for (int j = 0; j < 8; j++)
        if (j < DPT) ss += acc[j] * acc[j];
    red[t] = ss;
    __syncthreads();
    for (int s = 128; s > 0; s >>= 1) {
        if (t < s) red[t] += red[t + s];
        __syncthreads();
    }
    if (t == 0) s_scale = 1.f / fmaxf(sqrtf(red[0]), 1e-12f);
    __syncthreads();
    float sc = s_scale;
#pragma unroll
    for (int j = 0; j < 8; j++)
        if (j < DPT) g_wT[(size_t)c * Dn + t + (j << 8)] = acc[j] * sc;
}

// ---------------- launch ----------------
extern "C" void kernel_launch(void* const* d_in, const int* in_sizes, int n_in,
                              void* d_out, int out_size) {
    const float* z = (const float*)d_in[0];
    const float* W = (const float*)d_in[1];
    const int* pK = (const int*)d_in[2];

    double dd = sqrt((double)in_sizes[0] * (double)in_sizes[1] / (double)out_size);
    int Dn = (int)(dd + 0.5);
    int Bn = in_sizes[0] / Dn;
    int Cn = in_sizes[1] / Dn;
    int Nn = Bn + Cn;
    int Mp = ((Nn + 127) / 128) * 128;   // 5120
    int Cp = ((Cn + 127) / 128) * 128;   // 1024

    __nv_bfloat16 *Sp, *Bp, *Wp;
    float* Lp;
    cudaGetSymbolAddress((void**)&Sp, g_Sext);
    cudaGetSymbolAddress((void**)&Bp, g_Bext);
    cudaGetSymbolAddress((void**)&Wp, g_wText);
    cudaGetSymbolAddress((void**)&Lp, g_logits);

    cudaFuncSetAttribute(gemm_mma_kernel, cudaFuncAttributeMaxDynamicSharedMemorySize,
                         STAGES * STAGE_BYTES);

    // 1. split-bf16 [hi|lo] operands + fused row norms
    conv_supports_kernel<<<Mp, 256>>>(z, W, Bn, Cn, Nn, Dn);

    // 2. logits = [W;z] @ W^T
    {
        dim3 g(Cp / 128, Mp / 128);
        gemm_mma_kernel<<<g, 256, STAGES * STAGE_BYTES>>>(Sp, Bp, Lp, CP_CAP, Cn, Dn);
    }

    // 3. entropy + argmax
    ent_argmax_kernel<<<Nn, 256>>>(Lp, Nn, Cn, CP_CAP);

    // 4. per-class selection + prototypes
    build_weights_kernel<<<Cn, 256>>>(z, W, Nn, Bn, Cn, Dn, pK);

    // 5. weights -> split-bf16, then out = z @ weights
    conv_w_kernel<<<Cp, 256>>>(Cn, Dn);
    {
        dim3 g(Cp / 128, Bn / 128);
        gemm_mma_kernel<<<g, 256, STAGES * STAGE_BYTES>>>(Sp + (size_t)Cn * (2 * Dn), Wp,
                                                          (float*)d_out, Cn, Cn, Dn);
    }
}